// round 11
// baseline (speedup 1.0000x reference)
#include <cuda_runtime.h>
#include <cuda_fp16.h>
#include <math.h>

// x (32, 1, 720, 1024) f32 -> out (32, 1, 512, 512) f32
// out[z,y,xp] = (pi/720) * sum_v lerp(x[z,0,v,:], t),  t = xf*cos + yf*sin + 511.5
// t in [150.2, 872.8] => always in-bounds for nDct=1024.
//
// R8 = R6 inner loop (fp16 z-oct cells, half lerp HSUB2/HFMA2, f32 FADD accumulate)
//  + RY=2 / 8-row y-tiles -> 2048 CTAs (wave util 77% -> 86%)
//  + half-convert-at-load staging (R7's register trick) -> occ 4.
// R7's packed-FFMA2 accumulate reverted (it serialized F2F->mov->FFMA2).

#define NV   720
#define ND   1024
#define NVND (NV * ND)
#define NXI  512
#define NYI  512
#define WIN  72     // staged window cells per view (8-row tile: span ~67 + slack)
#define RY   2      // r-steps per thread (y stride 4) -> 8 y rows per warp
#define ZC   8      // z-slices per cell

__device__ float g_cos[NV];
__device__ float g_sin[NV];

__global__ void init_trig_kernel() {
    int v = blockIdx.x * blockDim.x + threadIdx.x;
    if (v < NV) {
        float th = (float)v * (float)(M_PI / (double)NV);
        g_cos[v] = cosf(th);
        g_sin[v] = sinf(th);
    }
}

// Must be computed identically by stager and consumers (same FP ops => it is).
__device__ __forceinline__ int calc_dmin(float c, float s, float xfmin, float yf0) {
    float xsel = (c >= 0.0f) ? xfmin : (xfmin + 63.0f);   // 64-wide x tile
    float tmin = fmaf(xsel, c, fmaf(yf0, s, 511.5f));     // s >= 0 on [0,pi)
    return (int)tmin - 1;                                 // tmin > 0: trunc==floor; -1 ulp guard
}

__global__ __launch_bounds__(256, 4) void backproject_kernel(
    const float* __restrict__ x, float* __restrict__ out)
{
    __shared__ uint4 cell[2][WIN];           // half8 z-oct cells, double-buffered (2.25 KB)
    __shared__ float s_cos[NV], s_sin[NV];   // 5.76 KB

    const int tid  = threadIdx.x;            // 256 threads = 8 warps
    const int lane = tid & 31;
    const int wrp  = tid >> 5;
    const int lx   = lane & 7;               // 8 x per warp
    const int ly   = lane >> 3;              // 4 y per warp

    for (int i = tid; i < NV; i += 256) { s_cos[i] = g_cos[i]; s_sin[i] = g_sin[i]; }

    const int xg = blockIdx.x * 64 + wrp * 8 + lx;   // 8 x-tiles of 64
    const int yb = blockIdx.y * 8 + ly;              // 64 y-tiles of 8; thread rows yb + 4r
    const int zq = blockIdx.z * ZC;                  // 4 z-octs

    const float xf    = (float)xg - 255.5f;
    const float ybf   = (float)yb - 255.5f;
    const float xfmin = (float)(blockIdx.x * 64) - 255.5f;
    const float yf0   = (float)(blockIdx.y * 8) - 255.5f;

    float acc[RY][ZC];                       // persistent f32 accumulators (16 regs)
#pragma unroll
    for (int r = 0; r < RY; r++)
#pragma unroll
        for (int zz = 0; zz < ZC; zz++) acc[r][zz] = 0.0f;

    // shared-window base as 32-bit shared address for asm LDS
    unsigned int cell_base;
    asm("{ .reg .u64 t; cvta.to.shared.u64 t, %1; cvt.u32.u64 %0, t; }"
        : "=r"(cell_base) : "l"((const void*)cell));

    // Staging role: 144 threads, each owns (cell sc, z-half zh) -> 4 z values.
    const int st_on = (tid < 2 * WIN);
    const int zh    = (tid >= WIN) ? 1 : 0;
    const int sc    = tid - zh * WIN;             // cell index 0..WIN-1
    const float* __restrict__ gsl = x + (size_t)(zq + zh * 4) * NVND;

    // Prefetch view 0 window (theta=0: c=1, s=0 exactly); convert to half
    // immediately (2 live regs per stager instead of 4).
    unsigned pu01 = 0, pu23 = 0;
    if (st_on) {
        int dm = calc_dmin(1.0f, 0.0f, xfmin, yf0);
        const float* g = gsl + dm + sc;           // view 0 row offset = 0
        __half2 h01 = __floats2half2_rn(g[0], g[NVND]);
        __half2 h23 = __floats2half2_rn(g[2 * NVND], g[3 * NVND]);
        pu01 = *reinterpret_cast<unsigned*>(&h01);
        pu23 = *reinterpret_cast<unsigned*>(&h23);
    }

    for (int v = 0; v < NV; v++) {
        const int buf = v & 1;
        if (st_on) {
            *reinterpret_cast<uint2*>(
                reinterpret_cast<unsigned*>(&cell[buf][sc]) + zh * 2) = make_uint2(pu01, pu23);
        }
        __syncthreads();   // single sync per view; double buffering covers WAR

        if (v + 1 < NV && st_on) {
            float c1 = s_cos[v + 1], s1 = s_sin[v + 1];
            int dm = calc_dmin(c1, s1, xfmin, yf0);
            const float* g = gsl + (size_t)(v + 1) * ND + dm + sc;
            __half2 h01 = __floats2half2_rn(g[0], g[NVND]);
            __half2 h23 = __floats2half2_rn(g[2 * NVND], g[3 * NVND]);
            pu01 = *reinterpret_cast<unsigned*>(&h01);
            pu23 = *reinterpret_cast<unsigned*>(&h23);
        }

        const float c = s_cos[v];
        const float s = s_sin[v];
        const int dmin = calc_dmin(c, s, xfmin, yf0);
        // u = t - dmin, in [0, WIN-2) for every pixel of this tile
        float u = fmaf(xf, c, fmaf(ybf, s, 511.5f - (float)dmin));
        const float s4 = 4.0f * s;                 // y stride 4 rows per r-step
        const unsigned int base = cell_base + (buf ? (unsigned)(WIN * 16) : 0u);

#pragma unroll
        for (int r = 0; r < RY; r++) {
            int   i0 = (int)u;                     // u > 0: trunc == floor
            float w  = u - (float)i0;
            __half2 wh2 = __float2half2_rn(w);     // one F2FP (broadcast pack)
            unsigned int a0 = base + (unsigned)i0 * 16u;
            uint4 A, B;
            asm("ld.shared.v4.b32 {%0,%1,%2,%3}, [%4];"
                : "=r"(A.x), "=r"(A.y), "=r"(A.z), "=r"(A.w) : "r"(a0));
            asm("ld.shared.v4.b32 {%0,%1,%2,%3}, [%4 + 16];"
                : "=r"(B.x), "=r"(B.y), "=r"(B.z), "=r"(B.w) : "r"(a0));
#pragma unroll
            for (int p = 0; p < 4; p++) {
                unsigned ua = (p == 0) ? A.x : (p == 1) ? A.y : (p == 2) ? A.z : A.w;
                unsigned ub = (p == 0) ? B.x : (p == 1) ? B.y : (p == 2) ? B.z : B.w;
                __half2 ha = *reinterpret_cast<__half2*>(&ua);
                __half2 hb = *reinterpret_cast<__half2*>(&ub);
                // feed-forward half lerp: l = a + w*(b - a); no persistent half state
                __half2 d  = __hsub2(hb, ha);
                __half2 l  = __hfma2(d, wh2, ha);
                float2 f   = __half22float2(l);
                acc[r][2 * p]     += f.x;
                acc[r][2 * p + 1] += f.y;
            }
            u += s4;
        }
    }

    const float scale = (float)(M_PI / (double)NV);
#pragma unroll
    for (int r = 0; r < RY; r++) {
        const int y = yb + 4 * r;
#pragma unroll
        for (int zz = 0; zz < ZC; zz++) {
            out[((size_t)(zq + zz) * NYI + y) * NXI + xg] = acc[r][zz] * scale;
        }
    }
}

extern "C" void kernel_launch(void* const* d_in, const int* in_sizes, int n_in,
                              void* d_out, int out_size)
{
    const float* x   = (const float*)d_in[0];
    float*       out = (float*)d_out;

    init_trig_kernel<<<(NV + 255) / 256, 256>>>();

    dim3 grid(8, 64, 4);   // x-tiles, y-tiles, z-octs = 2048 CTAs
    backproject_kernel<<<grid, 256>>>(x, out);
}

// round 12
// speedup vs baseline: 1.1231x; 1.1231x over previous
#include <cuda_runtime.h>
#include <cuda_fp16.h>
#include <math.h>

// x (32, 1, 720, 1024) f32 -> out (32, 1, 512, 512) f32
// out[z,y,xp] = (pi/720) * sum_v lerp(x[z,0,v,:], t),  t = xf*cos + yf*sin + 511.5
// t in [150.2, 872.8] => always in-bounds for nDct=1024.
//
// R9 = R6 tiling (1024 CTAs, RY=4, fp16 z-oct cells, windowed staging) with a
// LEAN half2 accumulation: 2 HFMA2 per z-pair per tap-pair, flushed to f32
// every NF=4 views with a minimal drain (2 F2F + 2 FADD + zero per pair).
// R5's version of this was instruction-bloated; this one adds only
// w0h2 = pack(1-w) per r-step. R8's small-tile split reverted (per-view
// overhead scales with CTA count).

#define NV   720
#define ND   1024
#define NVND (NV * ND)
#define NXI  512
#define NYI  512
#define WIN  80     // staged window cells per view (16-row tile: span ~67 + slack)
#define RY   4      // r-steps per thread (y stride 4) -> 16 y rows per warp
#define ZC   8      // z-slices per cell
#define NF   4      // views per half-accumulator flush (precision measured: 5.4e-4)

__device__ float g_cos[NV];
__device__ float g_sin[NV];

__global__ void init_trig_kernel() {
    int v = blockIdx.x * blockDim.x + threadIdx.x;
    if (v < NV) {
        float th = (float)v * (float)(M_PI / (double)NV);
        g_cos[v] = cosf(th);
        g_sin[v] = sinf(th);
    }
}

// Must be computed identically by stager and consumers (same FP ops => it is).
__device__ __forceinline__ int calc_dmin(float c, float s, float xfmin, float yf0) {
    float xsel = (c >= 0.0f) ? xfmin : (xfmin + 63.0f);   // 64-wide x tile
    float tmin = fmaf(xsel, c, fmaf(yf0, s, 511.5f));     // s >= 0 on [0,pi)
    return (int)tmin - 1;                                 // tmin > 0: trunc==floor; -1 ulp guard
}

__global__ __launch_bounds__(256, 3) void backproject_kernel(
    const float* __restrict__ x, float* __restrict__ out)
{
    __shared__ uint4 cell[2][WIN];           // half8 z-oct cells, double-buffered (2.5 KB)
    __shared__ float s_cos[NV], s_sin[NV];   // 5.76 KB

    const int tid  = threadIdx.x;            // 256 threads = 8 warps
    const int lane = tid & 31;
    const int wrp  = tid >> 5;
    const int lx   = lane & 7;               // 8 x per warp
    const int ly   = lane >> 3;              // 4 y per warp

    for (int i = tid; i < NV; i += 256) { s_cos[i] = g_cos[i]; s_sin[i] = g_sin[i]; }

    const int xg = blockIdx.x * 64 + wrp * 8 + lx;   // 8 x-tiles of 64
    const int yb = blockIdx.y * 16 + ly;             // 32 y-tiles of 16; thread rows yb + 4r
    const int zq = blockIdx.z * ZC;                  // 4 z-octs

    const float xf    = (float)xg - 255.5f;
    const float ybf   = (float)yb - 255.5f;
    const float xfmin = (float)(blockIdx.x * 64) - 255.5f;
    const float yf0   = (float)(blockIdx.y * 16) - 255.5f;

    float accf[RY][ZC];                      // persistent f32 accumulators (32 regs)
#pragma unroll
    for (int r = 0; r < RY; r++)
#pragma unroll
        for (int zz = 0; zz < ZC; zz++) accf[r][zz] = 0.0f;

    __half2 acch[RY][4];                     // half window accumulators (16 regs)
#pragma unroll
    for (int r = 0; r < RY; r++)
#pragma unroll
        for (int p = 0; p < 4; p++) acch[r][p] = __float2half2_rn(0.0f);

    // shared-window base as 32-bit shared address for asm LDS
    unsigned int cell_base;
    asm("{ .reg .u64 t; cvta.to.shared.u64 t, %1; cvt.u32.u64 %0, t; }"
        : "=r"(cell_base) : "l"((const void*)cell));

    // Staging role: 160 threads, each owns (cell sc, z-half zh) -> 4 z values.
    const int st_on = (tid < 2 * WIN);
    const int zh    = (tid >= WIN) ? 1 : 0;
    const int sc    = tid - zh * WIN;             // cell index 0..WIN-1
    const float* __restrict__ gsl = x + (size_t)(zq + zh * 4) * NVND;

    // Prefetch view 0 window (theta=0: c=1, s=0 exactly); convert to half at
    // load time (2 live regs per stager).
    unsigned pu01 = 0, pu23 = 0;
    if (st_on) {
        int dm = calc_dmin(1.0f, 0.0f, xfmin, yf0);
        const float* g = gsl + dm + sc;           // view 0 row offset = 0
        __half2 h01 = __floats2half2_rn(g[0], g[NVND]);
        __half2 h23 = __floats2half2_rn(g[2 * NVND], g[3 * NVND]);
        pu01 = *reinterpret_cast<unsigned*>(&h01);
        pu23 = *reinterpret_cast<unsigned*>(&h23);
    }

    for (int v = 0; v < NV; v++) {
        const int buf = v & 1;
        if (st_on) {
            *reinterpret_cast<uint2*>(
                reinterpret_cast<unsigned*>(&cell[buf][sc]) + zh * 2) = make_uint2(pu01, pu23);
        }
        __syncthreads();   // single sync per view; double buffering covers WAR

        if (v + 1 < NV && st_on) {
            float c1 = s_cos[v + 1], s1 = s_sin[v + 1];
            int dm = calc_dmin(c1, s1, xfmin, yf0);
            const float* g = gsl + (size_t)(v + 1) * ND + dm + sc;
            __half2 h01 = __floats2half2_rn(g[0], g[NVND]);
            __half2 h23 = __floats2half2_rn(g[2 * NVND], g[3 * NVND]);
            pu01 = *reinterpret_cast<unsigned*>(&h01);
            pu23 = *reinterpret_cast<unsigned*>(&h23);
        }

        const float c = s_cos[v];
        const float s = s_sin[v];
        const int dmin = calc_dmin(c, s, xfmin, yf0);
        // u = t - dmin, in [0, WIN-2) for every pixel of this tile
        float u = fmaf(xf, c, fmaf(ybf, s, 511.5f - (float)dmin));
        const float s4 = 4.0f * s;                 // y stride 4 rows per r-step
        const unsigned int base = cell_base + (buf ? (unsigned)(WIN * 16) : 0u);

#pragma unroll
        for (int r = 0; r < RY; r++) {
            int   i0 = (int)u;                     // u > 0: trunc == floor
            float w  = u - (float)i0;
            float w0 = 1.0f - w;
            __half2 wh2  = __float2half2_rn(w);    // F2FP broadcast pack
            __half2 w0h2 = __float2half2_rn(w0);   // F2FP broadcast pack
            unsigned int a0 = base + (unsigned)i0 * 16u;
            uint4 A, B;
            asm("ld.shared.v4.b32 {%0,%1,%2,%3}, [%4];"
                : "=r"(A.x), "=r"(A.y), "=r"(A.z), "=r"(A.w) : "r"(a0));
            asm("ld.shared.v4.b32 {%0,%1,%2,%3}, [%4 + 16];"
                : "=r"(B.x), "=r"(B.y), "=r"(B.z), "=r"(B.w) : "r"(a0));
#pragma unroll
            for (int p = 0; p < 4; p++) {
                unsigned ua = (p == 0) ? A.x : (p == 1) ? A.y : (p == 2) ? A.z : A.w;
                unsigned ub = (p == 0) ? B.x : (p == 1) ? B.y : (p == 2) ? B.z : B.w;
                __half2 ha = *reinterpret_cast<__half2*>(&ua);
                __half2 hb = *reinterpret_cast<__half2*>(&ub);
                acch[r][p] = __hfma2(ha, w0h2, acch[r][p]);
                acch[r][p] = __hfma2(hb, wh2,  acch[r][p]);
            }
            u += s4;
        }

        // Lean flush of half window accumulators into f32 every NF views
        if ((v & (NF - 1)) == (NF - 1)) {
#pragma unroll
            for (int r = 0; r < RY; r++)
#pragma unroll
                for (int p = 0; p < 4; p++) {
                    accf[r][2 * p]     += __low2float(acch[r][p]);
                    accf[r][2 * p + 1] += __high2float(acch[r][p]);
                    acch[r][p] = __float2half2_rn(0.0f);
                }
        }
    }

    const float scale = (float)(M_PI / (double)NV);
#pragma unroll
    for (int r = 0; r < RY; r++) {
        const int y = yb + 4 * r;
#pragma unroll
        for (int zz = 0; zz < ZC; zz++) {
            out[((size_t)(zq + zz) * NYI + y) * NXI + xg] = accf[r][zz] * scale;
        }
    }
}

extern "C" void kernel_launch(void* const* d_in, const int* in_sizes, int n_in,
                              void* d_out, int out_size)
{
    const float* x   = (const float*)d_in[0];
    float*       out = (float*)d_out;

    init_trig_kernel<<<(NV + 255) / 256, 256>>>();

    dim3 grid(8, 32, 4);   // x-tiles, y-tiles, z-octs = 1024 CTAs
    backproject_kernel<<<grid, 256>>>(x, out);
}

// round 14
// speedup vs baseline: 1.5864x; 1.4126x over previous
#include <cuda_runtime.h>
#include <cuda_fp16.h>
#include <math.h>

// x (32, 1, 720, 1024) f32 -> out (32, 1, 512, 512) f32
// out[z,y,xp] = (pi/720) * sum_v lerp(x[z,0,v,:], t),  t = xf*cos + yf*sin + 511.5
// t in [150.2, 872.8] => always in-bounds for nDct=1024.
//
// R10 = R6 consumer loop (fp16 z-oct cells, feed-forward half lerp, f32 FADD
// accumulate — the only loop shape that works) with staging replaced by:
//   1) a pre-convert kernel producing z-interleaved half cells
//      hx[zg][v][d][8z] (one pass, ~30 us), and
//   2) per-view single cp.async.bulk (TMA) of the 1280-byte contiguous window,
//      double-buffered over two mbarriers.
// Removes all staging instructions/registers from the SM -> occ 4 at 1024 CTAs
// (wave util 77% -> 86.5%).

#define NV   720
#define ND   1024
#define NVND (NV * ND)
#define NXI  512
#define NYI  512
#define WIN  80     // staged window cells per view (16-row tile: span ~67 + slack)
#define RY   4      // r-steps per thread (y stride 4) -> 16 y rows per warp
#define ZC   8      // z-slices per cell
#define WINB (WIN * 16)   // window bytes = 1280

__device__ float g_cos[NV];
__device__ float g_sin[NV];
// z-interleaved half sinogram: [zg][v][d][8z], 4*720*1024*8 half = 47.2 MB
__device__ __align__(16) __half g_hx[4 * NV * ND * 8];

__global__ void init_trig_kernel() {
    int v = blockIdx.x * blockDim.x + threadIdx.x;
    if (v < NV) {
        float th = (float)v * (float)(M_PI / (double)NV);
        g_cos[v] = cosf(th);
        g_sin[v] = sinf(th);
    }
}

// Convert + transpose: x[z][v][d] f32 -> g_hx[zg][v][d][zz] half (z = zg*8+zz)
__global__ __launch_bounds__(256) void convert_kernel(const float* __restrict__ x) {
    const int d  = blockIdx.x * 256 + threadIdx.x;
    const int v  = blockIdx.y;
    const int zg = blockIdx.z;
    __half2 h01 = __floats2half2_rn(x[((size_t)(zg * 8 + 0) * NV + v) * ND + d],
                                    x[((size_t)(zg * 8 + 1) * NV + v) * ND + d]);
    __half2 h23 = __floats2half2_rn(x[((size_t)(zg * 8 + 2) * NV + v) * ND + d],
                                    x[((size_t)(zg * 8 + 3) * NV + v) * ND + d]);
    __half2 h45 = __floats2half2_rn(x[((size_t)(zg * 8 + 4) * NV + v) * ND + d],
                                    x[((size_t)(zg * 8 + 5) * NV + v) * ND + d]);
    __half2 h67 = __floats2half2_rn(x[((size_t)(zg * 8 + 6) * NV + v) * ND + d],
                                    x[((size_t)(zg * 8 + 7) * NV + v) * ND + d]);
    uint4 pk;
    pk.x = *reinterpret_cast<unsigned*>(&h01);
    pk.y = *reinterpret_cast<unsigned*>(&h23);
    pk.z = *reinterpret_cast<unsigned*>(&h45);
    pk.w = *reinterpret_cast<unsigned*>(&h67);
    *reinterpret_cast<uint4*>(&g_hx[(((size_t)zg * NV + v) * ND + d) * 8]) = pk;
}

// Must be computed identically by TMA issuer and consumers (same FP ops => it is).
__device__ __forceinline__ int calc_dmin(float c, float s, float xfmin, float yf0) {
    float xsel = (c >= 0.0f) ? xfmin : (xfmin + 63.0f);   // 64-wide x tile
    float tmin = fmaf(xsel, c, fmaf(yf0, s, 511.5f));     // s >= 0 on [0,pi)
    return (int)tmin - 1;                                 // tmin > 0: trunc==floor; -1 ulp guard
}

__device__ __forceinline__ void mbar_wait(unsigned mbar, unsigned phase) {
    unsigned done;
    do {
        asm volatile(
            "{\n\t.reg .pred p;\n\t"
            "mbarrier.try_wait.parity.acquire.cta.shared::cta.b64 p, [%1], %2, 0x989680;\n\t"
            "selp.b32 %0, 1, 0, p;\n\t}"
            : "=r"(done) : "r"(mbar), "r"(phase) : "memory");
    } while (!done);
}

__global__ __launch_bounds__(256, 4) void backproject_kernel(
    float* __restrict__ out)
{
    __shared__ __align__(16) char cellraw[2][WINB];  // half8 windows, double-buffered (2.5 KB)
    __shared__ float s_cos[NV], s_sin[NV];           // 5.76 KB
    __shared__ __align__(8) unsigned long long mbar[2];

    const int tid  = threadIdx.x;            // 256 threads = 8 warps
    const int lane = tid & 31;
    const int wrp  = tid >> 5;
    const int lx   = lane & 7;               // 8 x per warp
    const int ly   = lane >> 3;              // 4 y per warp

    for (int i = tid; i < NV; i += 256) { s_cos[i] = g_cos[i]; s_sin[i] = g_sin[i]; }

    const int xg = blockIdx.x * 64 + wrp * 8 + lx;   // 8 x-tiles of 64
    const int yb = blockIdx.y * 16 + ly;             // 32 y-tiles of 16; thread rows yb + 4r
    const int zg = blockIdx.z;                       // 4 z-octs

    const float xf    = (float)xg - 255.5f;
    const float ybf   = (float)yb - 255.5f;
    const float xfmin = (float)(blockIdx.x * 64) - 255.5f;
    const float yf0   = (float)(blockIdx.y * 16) - 255.5f;

    float acc[RY][ZC];                       // persistent f32 accumulators (32 regs)
#pragma unroll
    for (int r = 0; r < RY; r++)
#pragma unroll
        for (int zz = 0; zz < ZC; zz++) acc[r][zz] = 0.0f;

    unsigned int cell_base, mbar_base;
    asm("{ .reg .u64 t; cvta.to.shared.u64 t, %1; cvt.u32.u64 %0, t; }"
        : "=r"(cell_base) : "l"((const void*)cellraw));
    asm("{ .reg .u64 t; cvta.to.shared.u64 t, %1; cvt.u32.u64 %0, t; }"
        : "=r"(mbar_base) : "l"((const void*)mbar));

    const __half* __restrict__ hz = &g_hx[(size_t)zg * NVND * 8];

    if (tid == 0) {
        asm volatile("mbarrier.init.shared.b64 [%0], 1;" :: "r"(mbar_base)     : "memory");
        asm volatile("mbarrier.init.shared.b64 [%0], 1;" :: "r"(mbar_base + 8) : "memory");
    }
    __syncthreads();   // trig + mbarriers visible

    if (tid == 0) {
        // view 0 (c=1, s=0 exactly) -> buf 0
        {
            int dm = calc_dmin(1.0f, 0.0f, xfmin, yf0);
            const __half* src = hz + (size_t)dm * 8;   // v=0 row offset 0
            asm volatile("mbarrier.arrive.expect_tx.shared.b64 _, [%0], %1;"
                         :: "r"(mbar_base), "r"((unsigned)WINB) : "memory");
            asm volatile("cp.async.bulk.shared::cta.global.mbarrier::complete_tx::bytes "
                         "[%0], [%1], %2, [%3];"
                         :: "r"(cell_base), "l"(src), "r"((unsigned)WINB), "r"(mbar_base)
                         : "memory");
        }
        // view 1 -> buf 1
        {
            int dm = calc_dmin(s_cos[1], s_sin[1], xfmin, yf0);
            const __half* src = hz + ((size_t)ND + dm) * 8;
            asm volatile("mbarrier.arrive.expect_tx.shared.b64 _, [%0], %1;"
                         :: "r"(mbar_base + 8), "r"((unsigned)WINB) : "memory");
            asm volatile("cp.async.bulk.shared::cta.global.mbarrier::complete_tx::bytes "
                         "[%0], [%1], %2, [%3];"
                         :: "r"(cell_base + WINB), "l"(src), "r"((unsigned)WINB),
                            "r"(mbar_base + 8) : "memory");
        }
    }

    for (int v = 0; v < NV; v++) {
        const int buf = v & 1;
        mbar_wait(mbar_base + buf * 8, (unsigned)((v >> 1) & 1));

        const float c = s_cos[v];
        const float s = s_sin[v];
        const int dmin = calc_dmin(c, s, xfmin, yf0);
        // u = t - dmin, in [0, WIN-2) for every pixel of this tile
        float u = fmaf(xf, c, fmaf(ybf, s, 511.5f - (float)dmin));
        const float s4 = 4.0f * s;                 // y stride 4 rows per r-step
        const unsigned int base = cell_base + (unsigned)(buf * WINB);

#pragma unroll
        for (int r = 0; r < RY; r++) {
            int   i0 = (int)u;                     // u > 0: trunc == floor
            float w  = u - (float)i0;
            __half2 wh2 = __float2half2_rn(w);     // one F2FP (broadcast pack)
            unsigned int a0 = base + (unsigned)i0 * 16u;
            uint4 A, B;
            asm("ld.shared.v4.b32 {%0,%1,%2,%3}, [%4];"
                : "=r"(A.x), "=r"(A.y), "=r"(A.z), "=r"(A.w) : "r"(a0));
            asm("ld.shared.v4.b32 {%0,%1,%2,%3}, [%4 + 16];"
                : "=r"(B.x), "=r"(B.y), "=r"(B.z), "=r"(B.w) : "r"(a0));
#pragma unroll
            for (int p = 0; p < 4; p++) {
                unsigned ua = (p == 0) ? A.x : (p == 1) ? A.y : (p == 2) ? A.z : A.w;
                unsigned ub = (p == 0) ? B.x : (p == 1) ? B.y : (p == 2) ? B.z : B.w;
                __half2 ha = *reinterpret_cast<__half2*>(&ua);
                __half2 hb = *reinterpret_cast<__half2*>(&ub);
                // feed-forward half lerp: l = a + w*(b - a); no persistent half state
                __half2 d  = __hsub2(hb, ha);
                __half2 l  = __hfma2(d, wh2, ha);
                float2 f   = __half22float2(l);
                acc[r][2 * p]     += f.x;
                acc[r][2 * p + 1] += f.y;
            }
            u += s4;
        }

        __syncthreads();   // all threads done reading buf before refilling it

        if (v + 2 < NV && tid == 0) {
            float c2 = s_cos[v + 2], s2 = s_sin[v + 2];
            int dm = calc_dmin(c2, s2, xfmin, yf0);
            const __half* src = hz + ((size_t)(v + 2) * ND + dm) * 8;
            asm volatile("mbarrier.arrive.expect_tx.shared.b64 _, [%0], %1;"
                         :: "r"(mbar_base + buf * 8), "r"((unsigned)WINB) : "memory");
            asm volatile("cp.async.bulk.shared::cta.global.mbarrier::complete_tx::bytes "
                         "[%0], [%1], %2, [%3];"
                         :: "r"(base), "l"(src), "r"((unsigned)WINB),
                            "r"(mbar_base + buf * 8) : "memory");
        }
    }

    const float scale = (float)(M_PI / (double)NV);
#pragma unroll
    for (int r = 0; r < RY; r++) {
        const int y = yb + 4 * r;
#pragma unroll
        for (int zz = 0; zz < ZC; zz++) {
            out[((size_t)(zg * ZC + zz) * NYI + y) * NXI + xg] = acc[r][zz] * scale;
        }
    }
}

extern "C" void kernel_launch(void* const* d_in, const int* in_sizes, int n_in,
                              void* d_out, int out_size)
{
    const float* x   = (const float*)d_in[0];
    float*       out = (float*)d_out;

    init_trig_kernel<<<(NV + 255) / 256, 256>>>();
    convert_kernel<<<dim3(ND / 256, NV, 4), 256>>>(x);

    dim3 grid(8, 32, 4);   // x-tiles, y-tiles, z-octs = 1024 CTAs
    backproject_kernel<<<grid, 256>>>(out);
}